// round 17
// baseline (speedup 1.0000x reference)
#include <cuda_runtime.h>

#define L_LEN 8192

// alu-pipe compare-exchange (FMNMX x2)
__device__ __forceinline__ void ce(float& a, float& b) {
    float t = fminf(a, b);
    b = fmaxf(a, b);
    a = t;
}

// fma-pipe compare-exchange: min,max = ((a+b) -/+ |a-b|) * 0.5
// ~1ulp error on N(0,1) data; gate is 1e-3.
__device__ __forceinline__ void ce_fma(float& a, float& b) {
    float s  = a + b;
    float d  = a - b;
    float ad = fabsf(d);
    float mn = (s - ad) * 0.5f;
    float mx = (s + ad) * 0.5f;
    a = mn; b = mx;
}

// Median of 9 = median of {c0..c5 sorted commons} U {e0<=e1<=e2 extras}.
// c0 (rank<=3) / c5 (rank>=5) can't be rank-4 -> drop. min(c1,e0) is the min
// of the remaining 7, max(c4,e2) the max -> drop. Median = med5 of
// {max(c1,e0), c2<=c3, min(c4,e2), e1}; order the x/y pair, drop min(c2,xl)
// and max(c3,yh), median = med3(max(c2,xl), min(c3,yh), e1).
__device__ __forceinline__ float med9_pruned(float c1, float c2, float c3, float c4,
                                             float e0, float e1, float e2) {
    float x  = fmaxf(c1, e0);
    float y  = fminf(c4, e2);
    float xl = fminf(x, y);
    float yh = fmaxf(x, y);
    float lo = fmaxf(c2, xl);
    float hi = fminf(c3, yh);
    float mn = fminf(lo, hi);
    float mx = fmaxf(lo, hi);
    return fmaxf(mn, fminf(mx, e1));
}

// sort3 of {x} U {p<=q}: 4 alu ops. Returns (o0<=o1<=o2).
__device__ __forceinline__ void merge1into2(float x, float p, float q,
                                            float& o0, float& o1, float& o2) {
    o0 = fminf(x, p);
    float m = fmaxf(x, p);
    o1 = fminf(m, q);
    o2 = fmaxf(m, q);
}

// 4 medians for windows centered at the 4 middle positions of a 12-value span.
__device__ __forceinline__ float4 group4(const float* v) {
    // shared sorted common 6 (v[3..8]) -- sort3s + first merge on fma pipe
    float c0 = v[3], c1 = v[4], c2 = v[5], c3 = v[6], c4 = v[7], c5 = v[8];
    ce_fma(c0, c2); ce_fma(c0, c1); ce_fma(c1, c2);
    ce_fma(c3, c5); ce_fma(c3, c4); ce_fma(c4, c5);
    ce_fma(c0, c3); ce_fma(c2, c5);
    ce(c2, c3);
    ce(c1, c4);
    ce(c1, c2); ce(c3, c4);

    // shared sorted raw pairs (fma pipe)
    float s1 = v[1], s2 = v[2];  ce_fma(s1, s2);
    float t1 = v[9], t2 = v[10]; ce_fma(t1, t2);

    float e0, e1, e2;
    float4 o;
    merge1into2(v[0],  s1, s2, e0, e1, e2);  // extras {v0,v1,v2}
    o.x = med9_pruned(c1, c2, c3, c4, e0, e1, e2);
    merge1into2(v[9],  s1, s2, e0, e1, e2);  // extras {v1,v2,v9}
    o.y = med9_pruned(c1, c2, c3, c4, e0, e1, e2);
    merge1into2(v[2],  t1, t2, e0, e1, e2);  // extras {v2,v9,v10}
    o.z = med9_pruned(c1, c2, c3, c4, e0, e1, e2);
    merge1into2(v[11], t1, t2, e0, e1, e2);  // extras {v9,v10,v11}
    o.w = med9_pruned(c1, c2, c3, c4, e0, e1, e2);
    return o;
}

// 16 outputs per thread: 6 LDG.128 in, 4 STG.128 out, 4 independent groups.
// Reg cap 64 via (256,4): room for v[24]+temps without spilling.
__global__ __launch_bounds__(256, 4)
void median9_kernel(const float* __restrict__ x, float* __restrict__ out) {
    int gid = blockIdx.x * blockDim.x + threadIdx.x;
    int row = gid >> 9;                // 8192/16 = 512 groups per row
    int j   = (gid & 511) << 4;        // first of 16 output columns
    const float* rp = x + (size_t)row * L_LEN;

    float v[24];                       // inputs j-4 .. j+19
    if (j >= 16 && j <= L_LEN - 32) {  // interior: 6 aligned float4 loads
        #pragma unroll
        for (int q = 0; q < 6; q++) {
            float4 t = *reinterpret_cast<const float4*>(rp + j - 4 + 4 * q);
            v[4*q]   = t.x; v[4*q+1] = t.y; v[4*q+2] = t.z; v[4*q+3] = t.w;
        }
    } else {                           // replicate-pad boundary (2 threads/row)
        #pragma unroll
        for (int t = 0; t < 24; t++) {
            int idx = j - 4 + t;
            idx = idx < 0 ? 0 : (idx > L_LEN - 1 ? L_LEN - 1 : idx);
            v[t] = rp[idx];
        }
    }

    float* op = out + (size_t)row * L_LEN + j;
    // store each group as soon as it's done: keeps live set small, drains early
    *reinterpret_cast<float4*>(op)      = group4(v);
    *reinterpret_cast<float4*>(op + 4)  = group4(v + 4);
    *reinterpret_cast<float4*>(op + 8)  = group4(v + 8);
    *reinterpret_cast<float4*>(op + 12) = group4(v + 12);
}

extern "C" void kernel_launch(void* const* d_in, const int* in_sizes, int n_in,
                              void* d_out, int out_size) {
    const float* x = (const float*)d_in[0];
    float* out = (float*)d_out;
    int n = in_sizes[0];               // 32*64*8192 = 16777216
    int threads = n / 16;              // 16 outputs per thread
    int block = 256;
    int grid = (threads + block - 1) / block;
    median9_kernel<<<grid, block>>>(x, out);
}